// round 7
// baseline (speedup 1.0000x reference)
#include <cuda_runtime.h>

#define KCL   64
#define PD    32
#define NBLK  296
#define DETC  1e-16f
#define NENT  2240

typedef unsigned long long ull;

// per-block partials from mstep, layout [block][entry]:
// 0..2047 = M[k][p], 2048..2111 = N_k, 2112..2175 = E_k, 2176..2239 = S2_k
__device__ float g_scratch[NBLK * NENT];
__device__ float g_acc[NENT];

__device__ __forceinline__ ull pk2(float lo, float hi) {
    ull u; asm("mov.b64 %0, {%1,%2};" : "=l"(u) : "f"(lo), "f"(hi)); return u;
}
__device__ __forceinline__ void upk2(ull u, float& lo, float& hi) {
    asm("mov.b64 {%0,%1}, %2;" : "=f"(lo), "=f"(hi) : "l"(u));
}
__device__ __forceinline__ ull fma2(ull a, ull b, ull c) {
    ull d; asm("fma.rn.f32x2 %0, %1, %2, %3;" : "=l"(d) : "l"(a), "l"(b), "l"(c));
    return d;
}

// ============================================================================
// Kernel A — E-step: gamma = softmax-like weights, written straight to global.
// Thread roles: s = tid&7 (8-way cluster split, 8 clusters each),
//               gg = tid>>3 (point owner; thread's points are 32*i+gg).
// acc[8 points][4 cluster-pairs] = 64 regs. 2 CTAs/SM.
// ============================================================================
__global__ __launch_bounds__(256, 2)
void deeplpm_estep(const float* __restrict__ mu_phi,
                   const float* __restrict__ lcp_g,
                   const float* __restrict__ pi_k,
                   const float* __restrict__ mu_k,
                   const float* __restrict__ lck_g,
                   float* __restrict__ gamma_out, int N) {
    __shared__ ull   MUK2[1024];       // [p][pair] mu_k packed cluster-pairs
    __shared__ float ASMf[256 * 36];   // point rows, pitch 36 floats
    __shared__ float ECs[256];
    __shared__ float AK[64], ICOV[64], NB[64];

    const int tid = threadIdx.x;

    for (int idx = tid; idx < 1024; idx += 256) {
        int pr = idx & 31, p = idx >> 5;
        MUK2[p * 32 + pr] = pk2(mu_k[(2 * pr) * PD + p], mu_k[(2 * pr + 1) * PD + p]);
    }
    if (tid < KCL) {
        float lck = lck_g[tid];
        ICOV[tid] = __expf(-lck);
        AK[tid]   = pi_k[tid] * __expf(-16.0f * lck);
        float nb = 0.f;
        #pragma unroll
        for (int p = 0; p < PD; ++p) { float v = mu_k[tid * PD + p]; nb = fmaf(v, v, nb); }
        NB[tid] = nb;
    }

    const int s  = tid & 7;
    const int gg = tid >> 3;
    const int tiles = (N + 255) >> 8;

    for (int tile = blockIdx.x; tile < tiles; tile += gridDim.x) {
        __syncthreads();
        const int t0 = tile << 8;
        int vpts = N - t0; if (vpts > 256) vpts = 256;
        const int vflt = vpts * PD;

        // coalesced stage-in
        {
            const float* src = mu_phi + (size_t)t0 * PD;
            #pragma unroll
            for (int c = 0; c < 8; ++c) {
                int idx = c * 1024 + tid * 4;
                float4 v = make_float4(0.f, 0.f, 0.f, 0.f);
                if (idx < vflt) v = *(const float4*)(src + idx);
                *(float4*)(ASMf + (idx >> 5) * 36 + (idx & 31)) = v;
            }
            int i = t0 + tid;
            ECs[tid] = (i < N) ? __expf(lcp_g[i]) : 0.f;
        }
        __syncthreads();

        // GEMM1: 8 points x 8 clusters (4 pairs) per thread
        ull acc[8][4];
        #pragma unroll
        for (int i = 0; i < 8; ++i)
            #pragma unroll
            for (int j = 0; j < 4; ++j) acc[i][j] = 0ull;
        ull na2[4] = {0ull, 0ull, 0ull, 0ull};

        #pragma unroll 2
        for (int pp = 0; pp < 16; ++pp) {
            float2 f[8];
            #pragma unroll
            for (int i = 0; i < 8; ++i)
                f[i] = *(const float2*)(ASMf + (32 * i + gg) * 36 + 2 * pp);
            #pragma unroll
            for (int i2 = 0; i2 < 4; ++i2) {
                ull tx = pk2(f[2 * i2].x, f[2 * i2 + 1].x);
                na2[i2] = fma2(tx, tx, na2[i2]);
                ull ty = pk2(f[2 * i2].y, f[2 * i2 + 1].y);
                na2[i2] = fma2(ty, ty, na2[i2]);
            }
            {
                const ulonglong2* mp = (const ulonglong2*)(MUK2 + (2 * pp) * 32 + 4 * s);
                ulonglong2 ma = mp[0], mb = mp[1];
                ull m[4] = {ma.x, ma.y, mb.x, mb.y};
                #pragma unroll
                for (int i = 0; i < 8; ++i) {
                    ull x = pk2(f[i].x, f[i].x);
                    #pragma unroll
                    for (int j = 0; j < 4; ++j) acc[i][j] = fma2(x, m[j], acc[i][j]);
                }
            }
            {
                const ulonglong2* mp = (const ulonglong2*)(MUK2 + (2 * pp + 1) * 32 + 4 * s);
                ulonglong2 ma = mp[0], mb = mp[1];
                ull m[4] = {ma.x, ma.y, mb.x, mb.y};
                #pragma unroll
                for (int i = 0; i < 8; ++i) {
                    ull x = pk2(f[i].y, f[i].y);
                    #pragma unroll
                    for (int j = 0; j < 4; ++j) acc[i][j] = fma2(x, m[j], acc[i][j]);
                }
            }
        }
        float nav[8];
        upk2(na2[0], nav[0], nav[1]); upk2(na2[1], nav[2], nav[3]);
        upk2(na2[2], nav[4], nav[5]); upk2(na2[3], nav[6], nav[7]);

        // epilogue: w for this thread's 8 clusters per point
        float ws[8];
        #pragma unroll
        for (int i = 0; i < 8; ++i) {
            float ec = ECs[32 * i + gg];
            float tP = 32.0f * ec;
            float w = 0.f;
            #pragma unroll
            for (int j = 0; j < 4; ++j) {
                int k0 = 8 * s + 2 * j;
                float d0, d1; upk2(acc[i][j], d0, d1);
                float sq0 = nav[i] - 2.0f * d0 + NB[k0];
                float sq1 = nav[i] - 2.0f * d1 + NB[k0 + 1];
                float w0 = AK[k0]     * __expf(-0.5f * ICOV[k0]     * (tP + sq0));
                float w1 = AK[k0 + 1] * __expf(-0.5f * ICOV[k0 + 1] * (tP + sq1));
                w += w0 + w1;
                acc[i][j] = pk2(w0, w1);
            }
            ws[i] = w;
        }
        // wsum across the 8 split lanes (s = low 3 bits of lane id)
        #pragma unroll
        for (int i = 0; i < 8; ++i) {
            ws[i] += __shfl_xor_sync(0xffffffffu, ws[i], 1);
            ws[i] += __shfl_xor_sync(0xffffffffu, ws[i], 2);
            ws[i] += __shfl_xor_sync(0xffffffffu, ws[i], 4);
        }
        // gamma = w/wsum + DET  -> direct global store (thread owns 32B slice)
        #pragma unroll
        for (int i = 0; i < 8; ++i) {
            int pt = t0 + 32 * i + gg;
            if (pt < N) {
                float rs = 1.0f / ws[i];
                ull rs2 = pk2(rs, rs), dt2 = pk2(DETC, DETC);
                ull h0 = fma2(acc[i][0], rs2, dt2);
                ull h1 = fma2(acc[i][1], rs2, dt2);
                ull h2 = fma2(acc[i][2], rs2, dt2);
                ull h3 = fma2(acc[i][3], rs2, dt2);
                float4 v0, v1;
                upk2(h0, v0.x, v0.y); upk2(h1, v0.z, v0.w);
                upk2(h2, v1.x, v1.y); upk2(h3, v1.z, v1.w);
                float* gd = gamma_out + (size_t)pt * KCL + s * 8;
                *(float4*)gd = v0;
                *(float4*)(gd + 4) = v1;
            }
        }
    }
}

// ============================================================================
// Kernel B — M-step: streaming gamma^T @ mu_phi + stats, no smem in hot loop.
// Warp handles one point at a time, lanes = 8 kblk x 4 pblk.
// macc[8k][4 p-pairs] = 64 regs. 2 CTAs/SM.
// ============================================================================
__global__ __launch_bounds__(256, 2)
void deeplpm_mstep(const float* __restrict__ mu_phi,
                   const float* __restrict__ lcp_g,
                   const float* __restrict__ gamma,
                   int N) {
    extern __shared__ unsigned char smB[];
    const int tid = threadIdx.x;
    const int kb = tid & 7;
    const int pb = (tid >> 3) & 3;
    const int w  = tid >> 5;

    ull macc[8][4];
    #pragma unroll
    for (int kk = 0; kk < 8; ++kk)
        #pragma unroll
        for (int j = 0; j < 4; ++j) macc[kk][j] = 0ull;
    ull sN[4] = {0ull,0ull,0ull,0ull};
    ull sE[4] = {0ull,0ull,0ull,0ull};
    ull sS[4] = {0ull,0ull,0ull,0ull};

    const int gw = blockIdx.x * 8 + w;
    const int nw = gridDim.x * 8;

    for (int pt0 = gw * 32; pt0 < N; pt0 += nw * 32) {
        int lim = N - pt0; if (lim > 32) lim = 32;
        #pragma unroll 2
        for (int u = 0; u < lim; ++u) {
            int pt = pt0 + u;
            const float4* gp = (const float4*)(gamma + (size_t)pt * KCL + kb * 8);
            float4 ga = gp[0], gb = gp[1];
            const ulonglong2* xp = (const ulonglong2*)(mu_phi + (size_t)pt * PD + pb * 8);
            ulonglong2 xa = xp[0], xb = xp[1];
            ull xu[4] = {xa.x, xa.y, xb.x, xb.y};
            ull nap2 = 0ull;
            #pragma unroll
            for (int j = 0; j < 4; ++j) nap2 = fma2(xu[j], xu[j], nap2);
            float nlo, nhi; upk2(nap2, nlo, nhi);
            float nap = nlo + nhi;                 // partial ||x||^2 (this p-slice)
            float gv[8] = {ga.x, ga.y, ga.z, ga.w, gb.x, gb.y, gb.z, gb.w};
            #pragma unroll
            for (int kk = 0; kk < 8; ++kk) {
                ull g2 = pk2(gv[kk], gv[kk]);
                #pragma unroll
                for (int j = 0; j < 4; ++j) macc[kk][j] = fma2(g2, xu[j], macc[kk][j]);
            }
            ull np2 = pk2(nap, nap);
            #pragma unroll
            for (int q = 0; q < 4; ++q) {
                ull gp2 = pk2(gv[2 * q], gv[2 * q + 1]);
                sS[q] = fma2(gp2, np2, sS[q]);     // S2 partial (sums over pb later)
            }
            if (pb == 0) {
                float ec = __expf(lcp_g[pt]);
                ull e2 = pk2(ec, ec);
                ull one2 = pk2(1.0f, 1.0f);
                #pragma unroll
                for (int q = 0; q < 4; ++q) {
                    ull gp2 = pk2(gv[2 * q], gv[2 * q + 1]);
                    sN[q] = fma2(gp2, one2, sN[q]);
                    sE[q] = fma2(gp2, e2, sE[q]);
                }
            }
        }
    }

    // ---- block combine -> g_scratch ----
    ull* SB = (ull*)smB;                       // 256 * 32 ull = 64 KB
    #pragma unroll
    for (int kk = 0; kk < 8; ++kk)
        #pragma unroll
        for (int j = 0; j < 4; ++j)
            SB[tid * 32 + kk * 4 + j] = macc[kk][j];
    __syncthreads();

    float* my = g_scratch + (size_t)blockIdx.x * NENT;
    for (int o = tid; o < 1024; o += 256) {
        int okb = o >> 7, okk = (o >> 4) & 7, opb = (o >> 2) & 3, oj = o & 3;
        float s0 = 0.f, s1 = 0.f;
        #pragma unroll
        for (int ww = 0; ww < 8; ++ww) {
            float x0, x1;
            upk2(SB[(ww * 32 + opb * 8 + okb) * 32 + okk * 4 + oj], x0, x1);
            s0 += x0; s1 += x1;
        }
        int k = okb * 8 + okk, p = opb * 8 + 2 * oj;
        my[k * PD + p]     = s0;
        my[k * PD + p + 1] = s1;
    }
    __syncthreads();
    #pragma unroll
    for (int q = 0; q < 4; ++q) {
        SB[tid * 12 + q]     = sN[q];
        SB[tid * 12 + 4 + q] = sE[q];
        SB[tid * 12 + 8 + q] = sS[q];
    }
    __syncthreads();
    if (tid < KCL) {
        int okb = tid >> 3, okk = tid & 7, q = okk >> 1, h = okk & 1;
        float n = 0.f, e = 0.f, s2 = 0.f;
        for (int ww = 0; ww < 8; ++ww) {
            int tp0 = ww * 32 + okb;               // pb == 0 lane
            float lo, hi;
            upk2(SB[tp0 * 12 + q], lo, hi);        n += h ? hi : lo;
            upk2(SB[tp0 * 12 + 4 + q], lo, hi);    e += h ? hi : lo;
            #pragma unroll
            for (int opb = 0; opb < 4; ++opb) {
                int ti = ww * 32 + opb * 8 + okb;
                upk2(SB[ti * 12 + 8 + q], lo, hi); s2 += h ? hi : lo;
            }
        }
        my[2048 + tid] = n;
        my[2112 + tid] = e;
        my[2176 + tid] = s2;
    }
}

// Stage 1: reduce g_scratch[nblk][NENT] -> g_acc[NENT], coalesced + MLP=4.
__global__ __launch_bounds__(256)
void deeplpm_reduce(int nblk) {
    int e = blockIdx.x * 256 + threadIdx.x;
    if (e >= NENT) return;
    const float* p = g_scratch + e;
    float s0 = 0.f, s1 = 0.f, s2 = 0.f, s3 = 0.f;
    int b = 0;
    for (; b + 4 <= nblk; b += 4) {
        s0 += p[(size_t)(b + 0) * NENT];
        s1 += p[(size_t)(b + 1) * NENT];
        s2 += p[(size_t)(b + 2) * NENT];
        s3 += p[(size_t)(b + 3) * NENT];
    }
    for (; b < nblk; ++b) s0 += p[(size_t)b * NENT];
    g_acc[e] = (s0 + s1) + (s2 + s3);
}

// Stage 2: final per-cluster math.
__global__ __launch_bounds__(64)
void deeplpm_finalize(float* __restrict__ pi_out,
                      float* __restrict__ mu_out,
                      float* __restrict__ lc_out,
                      int N) {
    int t = threadIdx.x;
    if (t >= KCL) return;
    float Nk = g_acc[2048 + t];
    float Ek = g_acc[2112 + t];
    float Sk = g_acc[2176 + t];
    pi_out[t] = Nk / (float)N;
    float inv = 1.0f / Nk;
    float nm2 = 0.0f;
    #pragma unroll
    for (int p = 0; p < PD; ++p) {
        float m = g_acc[t * PD + p] * inv;
        mu_out[t * PD + p] = m;
        nm2 = fmaf(m, m, nm2);
    }
    float cov = (32.0f * Ek + Sk - Nk * nm2) / (32.0f * Nk);
    lc_out[t] = logf(cov);
}

extern "C" void kernel_launch(void* const* d_in, const int* in_sizes, int n_in,
                              void* d_out, int out_size) {
    const float* mu_phi = (const float*)d_in[0];
    const float* lcp    = (const float*)d_in[1];
    const float* pi_k   = (const float*)d_in[2];
    const float* mu_k   = (const float*)d_in[3];
    const float* lck    = (const float*)d_in[4];
    const int N = in_sizes[0] / PD;

    float* out     = (float*)d_out;
    float* gamma_o = out;
    float* pi_o    = out + (size_t)N * KCL;
    float* mu_o    = pi_o + KCL;
    float* lc_o    = mu_o + KCL * PD;

    cudaFuncSetAttribute(deeplpm_mstep,
                         cudaFuncAttributeMaxDynamicSharedMemorySize, 65536);

    deeplpm_estep<<<NBLK, 256>>>(mu_phi, lcp, pi_k, mu_k, lck, gamma_o, N);
    deeplpm_mstep<<<NBLK, 256, 65536>>>(mu_phi, lcp, gamma_o, N);
    deeplpm_reduce<<<(NENT + 255) / 256, 256>>>(NBLK);
    deeplpm_finalize<<<1, 64>>>(pi_o, mu_o, lc_o, N);
}

// round 8
// speedup vs baseline: 1.6214x; 1.6214x over previous
#include <cuda_runtime.h>

#define KCL   64
#define PD    32
#define NBLK  296
#define TILE  256
#define DETC  1e-16f
#define NENT  2240

typedef unsigned long long ull;

// ---- shared memory layout (bytes) ----
#define OFF_MUK2 0          // ull[1024]  mu_k packed cluster-pairs [p][pair]  8192 B
#define OFF_ASM  8192       // 256 rows * 18 ull (mu_phi, pitch 36 floats)   36864 B
#define OFF_GT   45056      // float[64*257] gamma transposed [k][pt]        65792 B
#define OFF_EC   110848     // float[256] exp(lcp)
#define OFF_NA   111872     // float[256] ||x||^2
#define OFF_AK   112896     // float[64]
#define OFF_ICOV 113152     // float[64]
#define OFF_NB   113408     // float[64]
#define SMEM_BYTES 113664

// per-block partials, layout [block][entry]:
// 0..2047 = M[k][p], 2048..2111 = N_k, 2112..2175 = E_k, 2176..2239 = S2_k
__device__ float g_scratch[NBLK * NENT];
__device__ float g_acc[NENT];

__device__ __forceinline__ ull pk2(float lo, float hi) {
    ull u; asm("mov.b64 %0, {%1,%2};" : "=l"(u) : "f"(lo), "f"(hi)); return u;
}
__device__ __forceinline__ void upk2(ull u, float& lo, float& hi) {
    asm("mov.b64 {%0,%1}, %2;" : "=f"(lo), "=f"(hi) : "l"(u));
}
__device__ __forceinline__ ull fma2(ull a, ull b, ull c) {
    ull d; asm("fma.rn.f32x2 %0, %1, %2, %3;" : "=l"(d) : "l"(a), "l"(b), "l"(c));
    return d;
}

__global__ __launch_bounds__(256, 1)
void deeplpm_main(const float* __restrict__ mu_phi,
                  const float* __restrict__ lcp_g,
                  const float* __restrict__ pi_k,
                  const float* __restrict__ mu_k,
                  const float* __restrict__ lck_g,
                  float* __restrict__ gamma_out,
                  int N) {
    extern __shared__ unsigned char sm[];
    ull*   MUK2 = (ull*)(sm + OFF_MUK2);
    float* ASMf = (float*)(sm + OFF_ASM);   // pitch 36 floats per point
    ull*   ASMu = (ull*)(sm + OFF_ASM);     // pitch 18 ull per point
    float* GT   = (float*)(sm + OFF_GT);
    float* ECs  = (float*)(sm + OFF_EC);
    float* NAs  = (float*)(sm + OFF_NA);
    float* AK   = (float*)(sm + OFF_AK);
    float* ICOV = (float*)(sm + OFF_ICOV);
    float* NB   = (float*)(sm + OFF_NB);

    const int tid = threadIdx.x;

    // ---- init tables ----
    for (int idx = tid; idx < 1024; idx += 256) {
        int pr = idx & 31, p = idx >> 5;
        MUK2[p * 32 + pr] = pk2(mu_k[(2 * pr) * PD + p], mu_k[(2 * pr + 1) * PD + p]);
    }
    if (tid < KCL) {
        float lck = lck_g[tid];
        ICOV[tid] = __expf(-lck);
        AK[tid]   = pi_k[tid] * __expf(-16.0f * lck);
        float nb = 0.0f;
        #pragma unroll
        for (int p = 0; p < PD; ++p) { float v = mu_k[tid * PD + p]; nb = fmaf(v, v, nb); }
        NB[tid] = nb;
    }

    // GEMM2 roles (R3 scheme): 4 point-quarters (q) x 32 kp x 2 ph
    const int q  = tid >> 6;
    const int r  = tid & 63;
    const int kp = r >> 1;
    const int ph = r & 1;
    const int gr0 = (2 * kp) * 257;
    const int gr1 = (2 * kp + 1) * 257;

    ull macc0[8], macc1[8];
    #pragma unroll
    for (int j = 0; j < 8; ++j) { macc0[j] = 0ull; macc1[j] = 0ull; }
    float nacc = 0.0f, eacc = 0.0f, sacc = 0.0f;

    const int tiles = (N + TILE - 1) >> 8;

    for (int tile = blockIdx.x; tile < tiles; tile += gridDim.x) {
        __syncthreads();   // previous iteration's readers done before overwrite
        const int t0 = tile << 8;
        int vpts = N - t0; if (vpts > TILE) vpts = TILE;
        const int vflt = vpts * PD;
        const int i = t0 + tid;
        const bool valid = i < N;

        // ---- coalesced stage-in: mu_phi -> ASM (pitch 36, 16B-aligned rows)
        {
            const float* src = mu_phi + (size_t)t0 * PD;
            #pragma unroll
            for (int c = 0; c < 8; ++c) {
                int idx = c * 1024 + tid * 4;
                float4 v = make_float4(0.f, 0.f, 0.f, 0.f);
                if (idx < vflt) v = *(const float4*)(src + idx);
                *(float4*)(ASMf + (idx >> 5) * 36 + (idx & 31)) = v;
            }
            ECs[tid] = valid ? __expf(lcp_g[i]) : 0.f;
        }
        __syncthreads();

        // ---- GEMM1: 1 point x 64 clusters, MUK2 via LDS.128 ----
        ull acc[32];
        #pragma unroll
        for (int k2 = 0; k2 < 32; ++k2) acc[k2] = 0ull;
        float na = 0.0f;
        const float* row = ASMf + tid * 36;
        #pragma unroll 4
        for (int pp = 0; pp < 16; ++pp) {
            float2 f = *(const float2*)(row + 2 * pp);
            na = fmaf(f.x, f.x, fmaf(f.y, f.y, na));
            ull ax = pk2(f.x, f.x), ay = pk2(f.y, f.y);
            const ulonglong2* mk0 = (const ulonglong2*)(MUK2 + (2 * pp) * 32);
            const ulonglong2* mk1 = (const ulonglong2*)(MUK2 + (2 * pp + 1) * 32);
            #pragma unroll
            for (int qq = 0; qq < 16; ++qq) {
                ulonglong2 m0 = mk0[qq];
                acc[2 * qq]     = fma2(ax, m0.x, acc[2 * qq]);
                acc[2 * qq + 1] = fma2(ax, m0.y, acc[2 * qq + 1]);
                ulonglong2 m1 = mk1[qq];
                acc[2 * qq]     = fma2(ay, m1.x, acc[2 * qq]);
                acc[2 * qq + 1] = fma2(ay, m1.y, acc[2 * qq + 1]);
            }
        }
        NAs[tid] = na;

        // ---- epilogue: w_k, wsum, gamma -> GT (transposed, conflict-free) ----
        {
            float ec = ECs[tid];
            float tP = 32.0f * ec;
            float wsum = 0.0f;
            #pragma unroll
            for (int k2 = 0; k2 < 32; ++k2) {
                float d0, d1; upk2(acc[k2], d0, d1);
                int k0 = 2 * k2;
                float sq0 = na - 2.0f * d0 + NB[k0];
                float sq1 = na - 2.0f * d1 + NB[k0 + 1];
                float w0 = AK[k0]     * __expf(-0.5f * ICOV[k0]     * (tP + sq0));
                float w1 = AK[k0 + 1] * __expf(-0.5f * ICOV[k0 + 1] * (tP + sq1));
                wsum += w0 + w1;
                acc[k2] = pk2(w0, w1);
            }
            float rs = valid ? 1.0f / wsum : 0.0f;
            float dt = valid ? DETC : 0.0f;
            ull rs2 = pk2(rs, rs), dt2 = pk2(dt, dt);
            #pragma unroll
            for (int k2 = 0; k2 < 32; ++k2) {
                float g0, g1;
                upk2(fma2(acc[k2], rs2, dt2), g0, g1);
                GT[(2 * k2) * 257 + tid]     = g0;
                GT[(2 * k2 + 1) * 257 + tid] = g1;
            }
        }
        __syncthreads();

        // ---- coalesced gamma store: GT -> global ----
        {
            float* gdst = gamma_out + (size_t)t0 * KCL;
            const int vf = vpts * KCL;
            #pragma unroll
            for (int c = 0; c < 16; ++c) {
                int o4 = c * 256 + tid;          // float4 index
                if (4 * o4 < vf) {
                    int pt = o4 >> 4, kq = (o4 & 15) * 4;
                    float4 v;
                    v.x = GT[(kq + 0) * 257 + pt];
                    v.y = GT[(kq + 1) * 257 + pt];
                    v.z = GT[(kq + 2) * 257 + pt];
                    v.w = GT[(kq + 3) * 257 + pt];
                    *(float4*)(gdst + 4 * o4) = v;
                }
            }
        }

        // ---- GEMM2: gamma^T @ mu_phi tile + stats ----
        {
            const int pb = q * 64;
            for (int u = 0; u < 64; ++u) {
                int pt = pb + u;
                float g0 = GT[gr0 + pt];
                float g1 = GT[gr1 + pt];
                ull ga = pk2(g0, g0), gb = pk2(g1, g1);
                const ulonglong2* ap = (const ulonglong2*)(ASMu + pt * 18 + ph * 8);
                ulonglong2 A0 = ap[0], A1 = ap[1], A2 = ap[2], A3 = ap[3];
                ull ar[8] = {A0.x, A0.y, A1.x, A1.y, A2.x, A2.y, A3.x, A3.y};
                #pragma unroll
                for (int j = 0; j < 8; ++j) {
                    macc0[j] = fma2(ga, ar[j], macc0[j]);
                    macc1[j] = fma2(gb, ar[j], macc1[j]);
                }
                float gk = ph ? g1 : g0;         // stats for cluster k == r
                nacc += gk;
                eacc = fmaf(gk, ECs[pt], eacc);
                sacc = fmaf(gk, NAs[pt], sacc);
            }
        }
    }

    // ---- block-level combine of the 4 point-quarter partials ----
    __syncthreads();
    ull*   SB  = (ull*)sm;                  // 256*16 ull = 32 KB (reuse)
    float* SSn = (float*)(sm + 32768);
    float* SSe = SSn + 256;
    float* SSs = SSe + 256;
    #pragma unroll
    for (int j = 0; j < 8; ++j) {
        SB[tid * 16 + j]     = macc0[j];
        SB[tid * 16 + 8 + j] = macc1[j];
    }
    SSn[tid] = nacc; SSe[tid] = eacc; SSs[tid] = sacc;
    __syncthreads();

    float* my = g_scratch + (size_t)blockIdx.x * NENT;
    for (int o = tid; o < 1024; o += 256) {
        int ro = o >> 4, jo = o & 15;
        float s0 = 0.0f, s1 = 0.0f;
        #pragma unroll
        for (int qq = 0; qq < 4; ++qq) {
            float x0, x1;
            upk2(SB[((qq << 6) | ro) * 16 + jo], x0, x1);
            s0 += x0; s1 += x1;
        }
        int kk = 2 * (ro >> 1) + (jo >> 3);
        int pp = 2 * (((ro & 1) << 3) + (jo & 7));
        my[kk * PD + pp]     = s0;
        my[kk * PD + pp + 1] = s1;
    }
    if (tid < KCL) {
        float n = 0.f, e = 0.f, s = 0.f;
        #pragma unroll
        for (int qq = 0; qq < 4; ++qq) {
            n += SSn[(qq << 6) | tid];
            e += SSe[(qq << 6) | tid];
            s += SSs[(qq << 6) | tid];
        }
        my[2048 + tid] = n;
        my[2112 + tid] = e;
        my[2176 + tid] = s;
    }
}

// Stage 1: reduce g_scratch[nblk][NENT] -> g_acc[NENT], coalesced + MLP=4.
__global__ __launch_bounds__(256)
void deeplpm_reduce(int nblk) {
    int e = blockIdx.x * 256 + threadIdx.x;
    if (e >= NENT) return;
    const float* p = g_scratch + e;
    float s0 = 0.f, s1 = 0.f, s2 = 0.f, s3 = 0.f;
    int b = 0;
    for (; b + 4 <= nblk; b += 4) {
        s0 += p[(size_t)(b + 0) * NENT];
        s1 += p[(size_t)(b + 1) * NENT];
        s2 += p[(size_t)(b + 2) * NENT];
        s3 += p[(size_t)(b + 3) * NENT];
    }
    for (; b < nblk; ++b) s0 += p[(size_t)b * NENT];
    g_acc[e] = (s0 + s1) + (s2 + s3);
}

// Stage 2: final per-cluster math.
__global__ __launch_bounds__(64)
void deeplpm_finalize(float* __restrict__ pi_out,
                      float* __restrict__ mu_out,
                      float* __restrict__ lc_out,
                      int N) {
    int t = threadIdx.x;
    if (t >= KCL) return;
    float Nk = g_acc[2048 + t];
    float Ek = g_acc[2112 + t];
    float Sk = g_acc[2176 + t];
    pi_out[t] = Nk / (float)N;
    float inv = 1.0f / Nk;
    float nm2 = 0.0f;
    #pragma unroll
    for (int p = 0; p < PD; ++p) {
        float m = g_acc[t * PD + p] * inv;
        mu_out[t * PD + p] = m;
        nm2 = fmaf(m, m, nm2);
    }
    float cov = (32.0f * Ek + Sk - Nk * nm2) / (32.0f * Nk);
    lc_out[t] = logf(cov);
}

extern "C" void kernel_launch(void* const* d_in, const int* in_sizes, int n_in,
                              void* d_out, int out_size) {
    const float* mu_phi = (const float*)d_in[0];
    const float* lcp    = (const float*)d_in[1];
    const float* pi_k   = (const float*)d_in[2];
    const float* mu_k   = (const float*)d_in[3];
    const float* lck    = (const float*)d_in[4];
    const int N = in_sizes[0] / PD;

    float* out     = (float*)d_out;
    float* gamma_o = out;
    float* pi_o    = out + (size_t)N * KCL;
    float* mu_o    = pi_o + KCL;
    float* lc_o    = mu_o + KCL * PD;

    int tiles = (N + TILE - 1) / TILE;
    int grid  = tiles < NBLK ? tiles : NBLK;

    cudaFuncSetAttribute(deeplpm_main,
                         cudaFuncAttributeMaxDynamicSharedMemorySize, SMEM_BYTES);

    deeplpm_main<<<grid, 256, SMEM_BYTES>>>(mu_phi, lcp, pi_k, mu_k, lck,
                                            gamma_o, N);
    deeplpm_reduce<<<(NENT + 255) / 256, 256>>>(grid);
    deeplpm_finalize<<<1, 64>>>(pi_o, mu_o, lc_o, N);
}